// round 16
// baseline (speedup 1.0000x reference)
#include <cuda_runtime.h>
#include <cuda_fp16.h>
#include <math.h>
#include <stdint.h>

// ---------------------------------------------------------------------------
// Problem constants
// ---------------------------------------------------------------------------
#define B_ 8
#define T_ 4096
#define D_ 512
#define M_TOTAL (B_ * T_)          // 32768
#define CHUNK 128
#define NCHUNK (T_ / CHUNK)        // 32
#define NSTH 8                     // k-stages (BK=64, fp16)

// ---------------------------------------------------------------------------
// Scratch
// ---------------------------------------------------------------------------
__device__ __half  g_hbufA[(size_t)M_TOTAL * D_];  // cum-mean -> later packed x
__device__ __half  g_hbufB[(size_t)M_TOTAL * D_];  // H, fp16 interleaved
__device__ float   g_agg[B_ * NCHUNK * D_];        // scan aggregates
__device__ float   g_inc[B_ * NCHUNK * D_];        // scan inclusives
__device__ int     g_flag[B_ * NCHUNK];            // 0=none 1=agg 2=inc
__device__ float   g_summ[B_ * D_];                // summ_proj
__device__ float   g_summ2[B_ * D_];               // summ_proj@W_out + b_out
__device__ float2  g_stats[(size_t)M_TOTAL * 8];   // per-(row,tile,n-half) sum/sq
__device__ __half  g_hWt[2 * (size_t)D_ * D_];     // [0]=W_hist^T il, [1]=Wc^T il

// ---------------------------------------------------------------------------
// Helpers
// ---------------------------------------------------------------------------
__device__ __forceinline__ uint32_t smem_u32(const void* p) {
    uint32_t a;
    asm("{ .reg .u64 t; cvta.to.shared.u64 t, %1; cvt.u32.u64 %0, t; }"
        : "=r"(a) : "l"(p));
    return a;
}
__device__ __forceinline__ void mma_f16_16x8x16(float* d, const uint32_t* a,
                                                const uint32_t* b) {
    asm volatile(
        "mma.sync.aligned.m16n8k16.row.col.f32.f16.f16.f32 "
        "{%0,%1,%2,%3}, {%4,%5,%6,%7}, {%8,%9}, {%0,%1,%2,%3};"
        : "+f"(d[0]), "+f"(d[1]), "+f"(d[2]), "+f"(d[3])
        : "r"(a[0]), "r"(a[1]), "r"(a[2]), "r"(a[3]),
          "r"(b[0]), "r"(b[1]));
}

#define CP_ASYNC16(dst, src) \
    asm volatile("cp.async.cg.shared.global [%0], [%1], 16;" \
                 :: "r"(dst), "l"(src) : "memory")
#define CP_COMMIT() asm volatile("cp.async.commit_group;" ::: "memory")
#define CP_WAIT1()  asm volatile("cp.async.wait_group 1;" ::: "memory")
#define CP_WAIT0()  asm volatile("cp.async.wait_group 0;" ::: "memory")

// fp16 k16-fragment interleave within a 64-wide k-stage
__device__ __forceinline__ int kpos64(int kk) {          // kk in [0,64)
    int g = kk >> 4, j = kk & 15;
    int lr = (j >> 1) & 3;
    int idx = ((j >> 3) << 1) | (j & 1);
    return (g >> 1) * 32 + lr * 8 + (g & 1) * 4 + idx;
}
__device__ __forceinline__ size_t ileave16(int m, int k) {   // offset in halves
    return ((size_t)((m >> 7) * NSTH + (k >> 6)) * 128 + (m & 127)) * 64
           + kpos64(k & 63);
}
__device__ __forceinline__ int swz8(int r) {
    return (((r & 1) << 2) | ((r >> 1) & 3));
}

// ---------------------------------------------------------------------------
// scan_kernel (launch 0): fused chunk-sum + decoupled-lookback prefix +
// cum-mean emit (fp16 interleaved). One DRAM read of dec; pass 2 hits L2.
// 256 blocks x 512 threads, all co-resident; lookback waits on lower ids only.
// ---------------------------------------------------------------------------
__global__ __launch_bounds__(512)
void scan_kernel(const float* __restrict__ dec) {
    __shared__ int sh_f;
    int bc = blockIdx.x;
    int b = bc / NCHUNK, c = bc % NCHUNK;
    int d = threadIdx.x;
    size_t base_in = ((size_t)(b * T_ + c * CHUNK)) * D_ + d;

    // pass 1: chunk total
    float s = 0.f;
    #pragma unroll 8
    for (int t = 0; t < CHUNK; ++t) s += dec[base_in + (size_t)t * D_];

    float basev = 0.f;
    if (c == 0) {
        g_inc[(size_t)bc * D_ + d] = s;
        __threadfence();
        __syncthreads();
        if (d == 0) atomicExch(&g_flag[bc], 2);
    } else {
        g_agg[(size_t)bc * D_ + d] = s;
        __threadfence();
        __syncthreads();
        if (d == 0) atomicExch(&g_flag[bc], 1);
        int j = c - 1;
        while (true) {
            if (d == 0) {
                int f;
                do { f = atomicAdd(&g_flag[b * NCHUNK + j], 0); } while (f == 0);
                sh_f = f;
            }
            __syncthreads();
            int f = sh_f;
            __syncthreads();
            if (f == 2) { basev += g_inc[(size_t)(b * NCHUNK + j) * D_ + d]; break; }
            basev += g_agg[(size_t)(b * NCHUNK + j) * D_ + d];
            --j;
        }
        g_inc[(size_t)bc * D_ + d] = basev + s;
        __threadfence();
        __syncthreads();
        if (d == 0) atomicExch(&g_flag[bc], 2);
    }

    // pass 2: emit running means (dec chunk is L2-hot)
    size_t obase = ((size_t)(bc * NSTH + (d >> 6)) * 128) * 64 + kpos64(d & 63);
    float run = basev;
    for (int t = 0; t < CHUNK; t += 8) {
        float v[8];
        #pragma unroll
        for (int u = 0; u < 8; ++u)
            v[u] = dec[base_in + (size_t)(t + u) * D_];
        int tt = c * CHUNK + t;
        #pragma unroll
        for (int u = 0; u < 8; ++u) {
            run += v[u];
            g_hbufA[obase + (size_t)(t + u) * 64] =
                __float2half_rn(run / (float)(tt + u + 1));
        }
    }
}

// ---------------------------------------------------------------------------
// pre0_kernel (launch 1): Wc=W2@W_out (128) + summ_proj (32). 160 blocks.
// ---------------------------------------------------------------------------
__global__ __launch_bounds__(512)
void pre0_kernel(const float* __restrict__ summ, const float* __restrict__ W1,
                 const float* __restrict__ W2, const float* __restrict__ W_out) {
    __shared__ float sh[6400];             // 25 KB (Wc: As 64x68 + Bs 64x32)
    int blk = blockIdx.x;
    int tid = threadIdx.x;

    if (blk < 128) {                       // ---- Wc = W2 @ W_out (64x32 tile) ----
        int widx = blk;
        int i0 = (widx & 7) * 64;
        int j0 = (widx >> 3) * 32;
        float* As = sh;                    // [64][68]
        float* Bs = sh + 64 * 68;          // [64][32]
        int r = tid >> 3;
        int c8 = (tid & 7) * 8;
        int bc4 = (tid & 7) * 4;
        int ti = tid >> 3;
        int tjg = tid & 7;
        float a4[4];
        #pragma unroll
        for (int j = 0; j < 4; ++j) a4[j] = 0.f;

        for (int k0 = 0; k0 < 512; k0 += 64) {
            __syncthreads();
            *(float4*)&As[r * 68 + c8]     = *(const float4*)&W2[(size_t)(i0 + r) * D_ + k0 + c8];
            *(float4*)&As[r * 68 + c8 + 4] = *(const float4*)&W2[(size_t)(i0 + r) * D_ + k0 + c8 + 4];
            if (bc4 < 32)
                *(float4*)&Bs[r * 32 + bc4] = *(const float4*)&W_out[(size_t)(k0 + r) * D_ + j0 + bc4];
            __syncthreads();
            #pragma unroll 8
            for (int kk = 0; kk < 64; ++kk) {
                float a = As[ti * 68 + kk];
                float4 b0 = *(const float4*)&Bs[kk * 32 + tjg * 4];
                a4[0] = fmaf(a, b0.x, a4[0]); a4[1] = fmaf(a, b0.y, a4[1]);
                a4[2] = fmaf(a, b0.z, a4[2]); a4[3] = fmaf(a, b0.w, a4[3]);
            }
        }
        __half* Wc = g_hWt + (size_t)D_ * D_;
        int ii = i0 + ti;
        int kp = kpos64(ii & 63);
        int khi = ii >> 6;
        #pragma unroll
        for (int j = 0; j < 4; ++j) {
            int jj = j0 + tjg * 4 + j;
            size_t off = ((size_t)((jj >> 7) * NSTH + khi)) * 8192
                         + (size_t)(jj & 127) * 64 + kp;
            Wc[off] = __float2half_rn(a4[j]);
        }
    } else {                               // ---- summ_proj (fp32) ----
        int sidx = blk - 128;
        int b = sidx >> 2;
        int n0 = (sidx & 3) * 128;
        float* s = sh;
        float* red = sh + 512;
        int nl = tid & 127;
        int kg = tid >> 7;
        for (int i = tid; i < D_; i += 512) s[i] = summ[b * D_ + i];
        __syncthreads();
        float acc = 0.f;
        int k0 = kg * 128;
        #pragma unroll 8
        for (int k = 0; k < 128; ++k)
            acc = fmaf(s[k0 + k], W1[(size_t)(k0 + k) * D_ + n0 + nl], acc);
        red[kg * 128 + nl] = acc;
        __syncthreads();
        if (kg == 0)
            g_summ[b * D_ + n0 + nl] =
                red[nl] + red[128 + nl] + red[256 + nl] + red[384 + nl];
    }
}

// ---------------------------------------------------------------------------
// prep_kernel (launch 2): W_hist transpose (256) + sp2 (32). 288 blocks.
// ---------------------------------------------------------------------------
__global__ __launch_bounds__(512)
void prep_kernel(const float* __restrict__ W_hist,
                 const float* __restrict__ W_out, const float* __restrict__ b_out) {
    __shared__ float sh[1056];
    int blk = blockIdx.x;
    int tid = threadIdx.x;

    if (blk < 256) {                       // ---- W_hist transpose+interleave ----
        int r = blk;
        int bx = (r & 15) * 32, by = (r >> 4) * 32;
        if (tid < 256) {
            int x = tid & 31, y = tid >> 5;
            float(*t)[33] = (float(*)[33])sh;
            #pragma unroll
            for (int i = 0; i < 32; i += 8)
                t[y + i][x] = W_hist[(size_t)(by + y + i) * D_ + bx + x];
            __syncthreads();
            #pragma unroll
            for (int i = 0; i < 32; i += 8)
                g_hWt[ileave16(bx + y + i, by + x)] = __float2half_rn(t[x][y + i]);
        } else {
            __syncthreads();
        }
    } else {                               // ---- sp2 = summ_proj@W_out + b_out ----
        int sidx = blk - 256;
        int b = sidx >> 2;
        int n0 = (sidx & 3) * 128;
        float* s = sh;
        float* red = sh + 512;
        int nl = tid & 127;
        int kg = tid >> 7;
        for (int i = tid; i < D_; i += 512) s[i] = g_summ[b * D_ + i];
        __syncthreads();
        float acc = 0.f;
        int k0 = kg * 128;
        #pragma unroll 8
        for (int k = 0; k < 128; ++k)
            acc = fmaf(s[k0 + k], W_out[(size_t)(k0 + k) * D_ + n0 + nl], acc);
        red[kg * 128 + nl] = acc;
        __syncthreads();
        if (kg == 0)
            g_summ2[b * D_ + n0 + nl] = b_out[n0 + nl] +
                red[nl] + red[128 + nl] + red[256 + nl] + red[384 + nl];
    }
}

// ---------------------------------------------------------------------------
// tc_gemm: mma.sync fp16 (m16n8k16), fully-unrolled 3-stage cp.async ring.
// Tile 128x128, BK=64, 8 warps, warp 32x64.
//   MODE 0: C(il,half) = half(tanh(acc + bias[col]))          packed 16B stores
//   MODE 2: C(il,half) = half(tanh(vecb[b][col]-acc)+resid)   packed 16B stores
//           + per-(row,tile,n-half) partial LN stats -> g_stats
// ---------------------------------------------------------------------------
#define GM_THREADS 256
#define TILE_M 128
#define TILE_N 128
#define STG 16384                          // 128 rows x 128B

#define SM_A   0
#define SM_B   (3 * STG)                   // 49152
#define GEMM_SMEM (SM_B + 3 * STG)         // 98304 = 96KB -> 2 CTAs/SM

template <int MODE>
__global__ __launch_bounds__(GM_THREADS, 2)
void tc_gemm(const __half* __restrict__ A, const __half* __restrict__ Bt,
             const float* __restrict__ vec, const float* __restrict__ resid,
             __half* __restrict__ Cv) {
    extern __shared__ char smem[];
    const uint32_t sbase = smem_u32(smem);

    const int tid = threadIdx.x;
    const int wid = tid >> 5, lane = tid & 31;
    const int row0 = blockIdx.y * TILE_M;
    const int col0 = blockIdx.x * TILE_N;
    const int wm = (wid & 3) * 32;
    const int wn = (wid >> 2) * 64;
    const int lq = lane >> 2;              // 0..7
    const int lr = lane & 3;               // 0..3

    const char* Ab = (const char*)A + (size_t)blockIdx.y * NSTH * 16384;
    const char* Bb = (const char*)Bt + (size_t)blockIdx.x * NSTH * 16384;
    const int frow = tid >> 3;             // 0..31
    const int fq = tid & 7;
    const uint32_t stchunk = (uint32_t)((fq ^ swz8(frow)) << 4);
    const uint32_t dA0 = sbase + SM_A + frow * 128 + stchunk;
    const uint32_t dB0 = sbase + SM_B + frow * 128 + stchunk;
    const size_t gsrc = (size_t)frow * 128 + fq * 16;

    const int swzl = swz8(lq);
    const int cc0 = (lr ^ swzl) << 4;
    const int cc1 = ((4 + lr) ^ swzl) << 4;

    const int aoff = (wm + lq) * 128;
    const int boff = (wn + lq) * 128;

    float acc[2][8][4];
    #pragma unroll
    for (int mt = 0; mt < 2; ++mt)
        #pragma unroll
        for (int nt = 0; nt < 8; ++nt)
            #pragma unroll
            for (int j = 0; j < 4; ++j) acc[mt][nt][j] = 0.f;

    #pragma unroll
    for (int p = 0; p < 2; ++p) {
        const char* as = Ab + (size_t)p * 16384;
        const char* bs = Bb + (size_t)p * 16384;
        #pragma unroll
        for (int i = 0; i < 4; ++i) {
            CP_ASYNC16(dA0 + p * STG + i * 4096, as + gsrc + (size_t)i * 4096);
            CP_ASYNC16(dB0 + p * STG + i * 4096, bs + gsrc + (size_t)i * 4096);
        }
        CP_COMMIT();
    }

    #pragma unroll
    for (int s = 0; s < NSTH; ++s) {
        const int buf = s % 3;
        if (s == NSTH - 1) { CP_WAIT0(); } else { CP_WAIT1(); }
        __syncthreads();
        if (s + 2 < NSTH) {
            const int bufn = (s + 2) % 3;
            const char* as = Ab + (size_t)(s + 2) * 16384;
            const char* bs = Bb + (size_t)(s + 2) * 16384;
            #pragma unroll
            for (int i = 0; i < 4; ++i) {
                CP_ASYNC16(dA0 + bufn * STG + i * 4096, as + gsrc + (size_t)i * 4096);
                CP_ASYNC16(dB0 + bufn * STG + i * 4096, bs + gsrc + (size_t)i * 4096);
            }
            CP_COMMIT();
        }

        const char* sa = smem + SM_A + buf * STG + aoff;
        const char* sb = smem + SM_B + buf * STG + boff;

        #pragma unroll
        for (int c = 0; c < 2; ++c) {
            const int co = c ? cc1 : cc0;
            uint4 qa0[2], qa1[2];
            #pragma unroll
            for (int mt = 0; mt < 2; ++mt) {
                qa0[mt] = *(const uint4*)(sa + mt * 2048 + co);
                qa1[mt] = *(const uint4*)(sa + mt * 2048 + 1024 + co);
            }
            uint32_t ag0[2][4], ag1[2][4];
            #pragma unroll
            for (int mt = 0; mt < 2; ++mt) {
                ag0[mt][0] = qa0[mt].x; ag0[mt][1] = qa1[mt].x;
                ag0[mt][2] = qa0[mt].y; ag0[mt][3] = qa1[mt].y;
                ag1[mt][0] = qa0[mt].z; ag1[mt][1] = qa1[mt].z;
                ag1[mt][2] = qa0[mt].w; ag1[mt][3] = qa1[mt].w;
            }
            uint4 pb = *(const uint4*)(sb + co);
            #pragma unroll
            for (int nt = 0; nt < 8; ++nt) {
                uint4 pc = pb;
                if (nt < 7)
                    pb = *(const uint4*)(sb + (nt + 1) * 1024 + co);
                uint32_t bg0[2] = { pc.x, pc.y };
                uint32_t bg1[2] = { pc.z, pc.w };
                mma_f16_16x8x16(acc[0][nt], ag0[0], bg0);
                mma_f16_16x8x16(acc[1][nt], ag0[1], bg0);
                mma_f16_16x8x16(acc[0][nt], ag1[0], bg1);
                mma_f16_16x8x16(acc[1][nt], ag1[1], bg1);
            }
        }
    }

    // ---------------- Epilogue: packed 16B interleaved stores ----------------
    const float* vbase = (MODE == 2) ? (vec + (size_t)(row0 / T_) * D_ + col0)
                                     : (vec + col0);
    const size_t tilebase = (size_t)blockIdx.y * NSTH * 8192;   // halves
    const int wnidx = wid >> 2;

    #pragma unroll
    for (int mt = 0; mt < 2; ++mt) {
        int r = wm + mt * 16 + lq;
        float s0 = 0.f, q0 = 0.f, s1 = 0.f, q1 = 0.f;
        #pragma unroll
        for (int pack = 0; pack < 2; ++pack) {
            int kabs = col0 + wn + pack * 32;
            size_t off = tilebase + (size_t)(kabs >> 6) * 8192
                         + (size_t)r * 64 + ((kabs & 63) >> 5) * 32 + lr * 8;
            __align__(16) __half2 h0[4];
            __align__(16) __half2 h1[4];
            #pragma unroll
            for (int q = 0; q < 4; ++q) {
                int nt = pack * 4 + q;
                int col = wn + nt * 8 + lr * 2;
                float b0 = vbase[col], b1 = vbase[col + 1];
                if (MODE == 0) {
                    h0[q] = __floats2half2_rn(tanhf(acc[mt][nt][0] + b0),
                                              tanhf(acc[mt][nt][1] + b1));
                    h1[q] = __floats2half2_rn(tanhf(acc[mt][nt][2] + b0),
                                              tanhf(acc[mt][nt][3] + b1));
                } else {
                    int row = row0 + r;
                    float2 rd0 = *(const float2*)(resid + (size_t)row * D_ + col0 + col);
                    float2 rd1 = *(const float2*)(resid + (size_t)(row + 8) * D_ + col0 + col);
                    float x0 = tanhf(b0 - acc[mt][nt][0]) + rd0.x;
                    float x1 = tanhf(b1 - acc[mt][nt][1]) + rd0.y;
                    float x2 = tanhf(b0 - acc[mt][nt][2]) + rd1.x;
                    float x3 = tanhf(b1 - acc[mt][nt][3]) + rd1.y;
                    s0 += x0 + x1; q0 += x0 * x0 + x1 * x1;
                    s1 += x2 + x3; q1 += x2 * x2 + x3 * x3;
                    h0[q] = __floats2half2_rn(x0, x1);
                    h1[q] = __floats2half2_rn(x2, x3);
                }
            }
            *(uint4*)(Cv + off)       = *(const uint4*)h0;
            *(uint4*)(Cv + off + 512) = *(const uint4*)h1;     // row r+8
        }
        if (MODE == 2) {
            #pragma unroll
            for (int o = 1; o <= 2; o <<= 1) {
                s0 += __shfl_xor_sync(0xffffffffu, s0, o);
                q0 += __shfl_xor_sync(0xffffffffu, q0, o);
                s1 += __shfl_xor_sync(0xffffffffu, s1, o);
                q1 += __shfl_xor_sync(0xffffffffu, q1, o);
            }
            if (lr == 0) {
                int row = row0 + r;
                g_stats[((size_t)row * 4 + blockIdx.x) * 2 + wnidx] =
                    make_float2(s0, q0);
                g_stats[((size_t)(row + 8) * 4 + blockIdx.x) * 2 + wnidx] =
                    make_float2(s1, q1);
            }
        }
    }
}

// ---------------------------------------------------------------------------
// LayerNorm normalize pass: stats precomputed; packed fp16 x -> fp32 out
// ---------------------------------------------------------------------------
__global__ __launch_bounds__(256)
void layernorm_kernel(const __half* __restrict__ X,
                      const float* __restrict__ gamma,
                      const float* __restrict__ beta,
                      float* __restrict__ out) {
    int row = blockIdx.x;
    int tid = threadIdx.x;

    float sum = 0.f, sq = 0.f;
    #pragma unroll
    for (int i = 0; i < 8; ++i) {
        float2 st = g_stats[(size_t)row * 8 + i];
        sum += st.x; sq += st.y;
    }
    float mu = sum * (1.0f / D_);
    float var = sq * (1.0f / D_) - mu * mu;
    float rstd = rsqrtf(var + 1e-6f);

    int p = tid * 2;
    int kb = p >> 6;
    int within = p & 63;
    int chunk = within >> 5;
    int p32 = within & 31;
    int lr = p32 >> 3;
    int q = (p32 >> 1) & 3;
    size_t addr = ((size_t)(row >> 7) * NSTH + kb) * 8192
                  + (size_t)(row & 127) * 64 + chunk * 32 + p32;
    __half2 hv = *(const __half2*)(X + addr);
    int col = kb * 64 + chunk * 32 + q * 8 + lr * 2;
    float2 g = *(const float2*)(gamma + col);
    float2 be = *(const float2*)(beta + col);
    float2 o;
    o.x = (__low2float(hv)  - mu) * rstd * g.x + be.x;
    o.y = (__high2float(hv) - mu) * rstd * g.y + be.y;
    *(float2*)(out + (size_t)row * D_ + col) = o;
}

// ---------------------------------------------------------------------------
// Launcher — launch index 3 = gemm0 (the ncu-profiled slot)
// ---------------------------------------------------------------------------
extern "C" void kernel_launch(void* const* d_in, const int* in_sizes, int n_in,
                              void* d_out, int out_size) {
    const float* summ   = (const float*)d_in[0];
    const float* dec    = (const float*)d_in[1];
    const float* W_hist = (const float*)d_in[2];
    const float* b_hist = (const float*)d_in[3];
    const float* W1     = (const float*)d_in[4];
    const float* W2     = (const float*)d_in[5];
    const float* W_out  = (const float*)d_in[6];
    const float* b_out  = (const float*)d_in[7];
    const float* gamma  = (const float*)d_in[8];
    const float* beta   = (const float*)d_in[9];
    float* out = (float*)d_out;

    __half *hbufA, *hbufB, *hwt;
    float *summ2;
    int* flags;
    cudaGetSymbolAddress((void**)&hbufA, g_hbufA);
    cudaGetSymbolAddress((void**)&hbufB, g_hbufB);
    cudaGetSymbolAddress((void**)&summ2, g_summ2);
    cudaGetSymbolAddress((void**)&hwt,   g_hWt);
    cudaGetSymbolAddress((void**)&flags, g_flag);
    __half* WtHist = hwt;
    __half* Wc     = hwt + (size_t)D_ * D_;

    cudaFuncSetAttribute(tc_gemm<0>, cudaFuncAttributeMaxDynamicSharedMemorySize, GEMM_SMEM);
    cudaFuncSetAttribute(tc_gemm<2>, cudaFuncAttributeMaxDynamicSharedMemorySize, GEMM_SMEM);

    // reset scan flags (graph-capturable async memset, no allocation)
    cudaMemsetAsync(flags, 0, B_ * NCHUNK * sizeof(int));

    // 0: fused chunk-scan + cum-mean -> hbufA (fp16, interleaved)
    scan_kernel<<<B_ * NCHUNK, D_>>>(dec);
    // 1: Wc=W2@W_out + summ_proj
    pre0_kernel<<<160, 512>>>(summ, W1, W2, W_out);
    // 2: W_hist transpose + sp2
    prep_kernel<<<288, 512>>>(W_hist, W_out, b_out);

    dim3 ggrid(D_ / TILE_N, M_TOTAL / TILE_M);   // (4, 256)
    // 3: H = tanh(cum @ W_hist + b_hist)
    tc_gemm<0><<<ggrid, GM_THREADS, GEMM_SMEM>>>(hbufA, WtHist, b_hist, nullptr, hbufB);
    // 4: x = tanh(sp2[b] - H @ Wc) + dec  (packed fp16 into hbufA) + LN stats
    tc_gemm<2><<<ggrid, GM_THREADS, GEMM_SMEM>>>(hbufB, Wc, summ2, dec, hbufA);

    // 5: LayerNorm normalize pass
    layernorm_kernel<<<M_TOTAL, 256>>>(hbufA, gamma, beta, out);
}

// round 17
// speedup vs baseline: 1.0268x; 1.0268x over previous
#include <cuda_runtime.h>
#include <cuda_fp16.h>
#include <math.h>
#include <stdint.h>

// ---------------------------------------------------------------------------
// Problem constants
// ---------------------------------------------------------------------------
#define B_ 8
#define T_ 4096
#define D_ 512
#define M_TOTAL (B_ * T_)          // 32768
#define CHUNK 128
#define NCHUNK (T_ / CHUNK)        // 32
#define NSTH 8                     // k-stages (BK=64, fp16)

// ---------------------------------------------------------------------------
// Scratch
// ---------------------------------------------------------------------------
__device__ __half  g_hbufA[(size_t)M_TOTAL * D_];  // cum-mean -> later packed x
__device__ __half  g_hbufB[(size_t)M_TOTAL * D_];  // H, fp16 interleaved
__device__ float   g_partial[B_ * NCHUNK * D_];
__device__ float   g_summ[B_ * D_];                // summ_proj
__device__ float   g_summ2[B_ * D_];               // summ_proj@W_out + b_out
__device__ float2  g_stats[(size_t)M_TOTAL * 8];   // per-(row,tile,n-half) sum/sq
__device__ int     g_sync[M_TOTAL / 128];          // per-row-block H-ready count
__device__ __half  g_hWt[2 * (size_t)D_ * D_];     // [0]=W_hist^T il, [1]=Wc^T il

// ---------------------------------------------------------------------------
// Helpers
// ---------------------------------------------------------------------------
__device__ __forceinline__ uint32_t smem_u32(const void* p) {
    uint32_t a;
    asm("{ .reg .u64 t; cvta.to.shared.u64 t, %1; cvt.u32.u64 %0, t; }"
        : "=r"(a) : "l"(p));
    return a;
}
__device__ __forceinline__ void mma_f16_16x8x16(float* d, const uint32_t* a,
                                                const uint32_t* b) {
    asm volatile(
        "mma.sync.aligned.m16n8k16.row.col.f32.f16.f16.f32 "
        "{%0,%1,%2,%3}, {%4,%5,%6,%7}, {%8,%9}, {%0,%1,%2,%3};"
        : "+f"(d[0]), "+f"(d[1]), "+f"(d[2]), "+f"(d[3])
        : "r"(a[0]), "r"(a[1]), "r"(a[2]), "r"(a[3]),
          "r"(b[0]), "r"(b[1]));
}

#define CP_ASYNC16(dst, src) \
    asm volatile("cp.async.cg.shared.global [%0], [%1], 16;" \
                 :: "r"(dst), "l"(src) : "memory")
#define CP_COMMIT() asm volatile("cp.async.commit_group;" ::: "memory")
#define CP_WAIT1()  asm volatile("cp.async.wait_group 1;" ::: "memory")
#define CP_WAIT0()  asm volatile("cp.async.wait_group 0;" ::: "memory")

// fp16 k16-fragment interleave within a 64-wide k-stage
__device__ __forceinline__ int kpos64(int kk) {          // kk in [0,64)
    int g = kk >> 4, j = kk & 15;
    int lr = (j >> 1) & 3;
    int idx = ((j >> 3) << 1) | (j & 1);
    return (g >> 1) * 32 + lr * 8 + (g & 1) * 4 + idx;
}
__device__ __forceinline__ size_t ileave16(int m, int k) {   // offset in halves
    return ((size_t)((m >> 7) * NSTH + (k >> 6)) * 128 + (m & 127)) * 64
           + kpos64(k & 63);
}
__device__ __forceinline__ int swz8(int r) {
    return (((r & 1) << 2) | ((r >> 1) & 3));
}

// ---------------------------------------------------------------------------
// pre0_kernel (launch 0): chunk_sum (256) + Wc=W2@W_out (128) + summ_proj (32)
// ---------------------------------------------------------------------------
__global__ __launch_bounds__(512)
void pre0_kernel(const float* __restrict__ dec,
                 const float* __restrict__ summ, const float* __restrict__ W1,
                 const float* __restrict__ W2, const float* __restrict__ W_out) {
    __shared__ float sh[6400];             // 25 KB (Wc: As 64x68 + Bs 64x32)
    int blk = blockIdx.x;
    int tid = threadIdx.x;

    if (blk < 256) {                       // ---- chunk sums ----
        int b = blk / NCHUNK, c = blk % NCHUNK;
        const float* p = dec + ((size_t)(b * T_ + c * CHUNK)) * D_ + tid;
        float s = 0.f;
        #pragma unroll 8
        for (int t = 0; t < CHUNK; ++t) s += p[(size_t)t * D_];
        g_partial[(size_t)blk * D_ + tid] = s;
    } else if (blk < 384) {                // ---- Wc = W2 @ W_out (64x32 tile) ----
        int widx = blk - 256;              // 0..127
        int i0 = (widx & 7) * 64;
        int j0 = (widx >> 3) * 32;
        float* As = sh;                    // [64][68]
        float* Bs = sh + 64 * 68;          // [64][32]
        int r = tid >> 3;
        int c8 = (tid & 7) * 8;
        int bc4 = (tid & 7) * 4;
        int ti = tid >> 3;
        int tjg = tid & 7;
        float a4[4];
        #pragma unroll
        for (int j = 0; j < 4; ++j) a4[j] = 0.f;

        for (int k0 = 0; k0 < 512; k0 += 64) {
            __syncthreads();
            *(float4*)&As[r * 68 + c8]     = *(const float4*)&W2[(size_t)(i0 + r) * D_ + k0 + c8];
            *(float4*)&As[r * 68 + c8 + 4] = *(const float4*)&W2[(size_t)(i0 + r) * D_ + k0 + c8 + 4];
            if (bc4 < 32)
                *(float4*)&Bs[r * 32 + bc4] = *(const float4*)&W_out[(size_t)(k0 + r) * D_ + j0 + bc4];
            __syncthreads();
            #pragma unroll 8
            for (int kk = 0; kk < 64; ++kk) {
                float a = As[ti * 68 + kk];
                float4 b0 = *(const float4*)&Bs[kk * 32 + tjg * 4];
                a4[0] = fmaf(a, b0.x, a4[0]); a4[1] = fmaf(a, b0.y, a4[1]);
                a4[2] = fmaf(a, b0.z, a4[2]); a4[3] = fmaf(a, b0.w, a4[3]);
            }
        }
        __half* Wc = g_hWt + (size_t)D_ * D_;
        int ii = i0 + ti;
        int kp = kpos64(ii & 63);
        int khi = ii >> 6;
        #pragma unroll
        for (int j = 0; j < 4; ++j) {
            int jj = j0 + tjg * 4 + j;
            size_t off = ((size_t)((jj >> 7) * NSTH + khi)) * 8192
                         + (size_t)(jj & 127) * 64 + kp;
            Wc[off] = __float2half_rn(a4[j]);
        }
    } else {                               // ---- summ_proj (fp32) ----
        int sidx = blk - 384;
        int b = sidx >> 2;
        int n0 = (sidx & 3) * 128;
        float* s = sh;
        float* red = sh + 512;
        int nl = tid & 127;
        int kg = tid >> 7;
        for (int i = tid; i < D_; i += 512) s[i] = summ[b * D_ + i];
        __syncthreads();
        float acc = 0.f;
        int k0 = kg * 128;
        #pragma unroll 8
        for (int k = 0; k < 128; ++k)
            acc = fmaf(s[k0 + k], W1[(size_t)(k0 + k) * D_ + n0 + nl], acc);
        red[kg * 128 + nl] = acc;
        __syncthreads();
        if (kg == 0)
            g_summ[b * D_ + n0 + nl] =
                red[nl] + red[128 + nl] + red[256 + nl] + red[384 + nl];
    }
}

// ---------------------------------------------------------------------------
// prep_kernel (launch 1): prefix (8) + W_hist transpose (256) + sp2 (32)
// ---------------------------------------------------------------------------
__global__ __launch_bounds__(512)
void prep_kernel(const float* __restrict__ W_hist,
                 const float* __restrict__ W_out, const float* __restrict__ b_out) {
    __shared__ float sh[1056];
    int blk = blockIdx.x;
    int tid = threadIdx.x;

    if (blk < 8) {
        int b = blk, d = tid;
        float run = 0.f;
        for (int c = 0; c < NCHUNK; ++c) {
            size_t idx = ((size_t)(b * NCHUNK + c)) * D_ + d;
            float v = g_partial[idx];
            g_partial[idx] = run;
            run += v;
        }
    } else if (blk < 264) {
        int r = blk - 8;
        int bx = (r & 15) * 32, by = (r >> 4) * 32;
        if (tid < 256) {
            int x = tid & 31, y = tid >> 5;
            float(*t)[33] = (float(*)[33])sh;
            #pragma unroll
            for (int i = 0; i < 32; i += 8)
                t[y + i][x] = W_hist[(size_t)(by + y + i) * D_ + bx + x];
            __syncthreads();
            #pragma unroll
            for (int i = 0; i < 32; i += 8)
                g_hWt[ileave16(bx + y + i, by + x)] = __float2half_rn(t[x][y + i]);
        } else {
            __syncthreads();
        }
    } else {
        int sidx = blk - 264;
        int b = sidx >> 2;
        int n0 = (sidx & 3) * 128;
        float* s = sh;
        float* red = sh + 512;
        int nl = tid & 127;
        int kg = tid >> 7;
        for (int i = tid; i < D_; i += 512) s[i] = g_summ[b * D_ + i];
        __syncthreads();
        float acc = 0.f;
        int k0 = kg * 128;
        #pragma unroll 8
        for (int k = 0; k < 128; ++k)
            acc = fmaf(s[k0 + k], W_out[(size_t)(k0 + k) * D_ + n0 + nl], acc);
        red[kg * 128 + nl] = acc;
        __syncthreads();
        if (kg == 0)
            g_summ2[b * D_ + n0 + nl] = b_out[n0 + nl] +
                red[nl] + red[128 + nl] + red[256 + nl] + red[384 + nl];
    }
}

// ---------------------------------------------------------------------------
// cum_mean (launch 2) -> g_hbufA (fp16, interleaved), 8x unrolled
// ---------------------------------------------------------------------------
__global__ void cum_mean_kernel(const float* __restrict__ dec) {
    int bc = blockIdx.x;
    int b = bc / NCHUNK, c = bc % NCHUNK;
    int d = threadIdx.x;
    size_t base = ((size_t)(b * T_ + c * CHUNK)) * D_ + d;
    float run = g_partial[(size_t)bc * D_ + d];
    size_t obase = ((size_t)(bc * NSTH + (d >> 6)) * 128) * 64 + kpos64(d & 63);
    #pragma unroll 1
    for (int t = 0; t < CHUNK; t += 8) {
        float v[8];
        #pragma unroll
        for (int u = 0; u < 8; ++u)
            v[u] = dec[base + (size_t)(t + u) * D_];
        int tt = c * CHUNK + t;
        #pragma unroll
        for (int u = 0; u < 8; ++u) {
            run += v[u];
            g_hbufA[obase + (size_t)(t + u) * 64] =
                __float2half_rn(run / (float)(tt + u + 1));
        }
    }
}

// ---------------------------------------------------------------------------
// gemm_tile<MODE>: one 128x128 output tile, 3-stage cp.async ring.
//   MODE 0: C(il,half) = half(tanh(acc + bias[col]))          packed 16B stores
//   MODE 2: C(il,half) = half(tanh(vecb[b][col]-acc)+resid)   + LN stats
// ---------------------------------------------------------------------------
#define GM_THREADS 256
#define TILE_M 128
#define TILE_N 128
#define STG 16384                          // 128 rows x 128B

#define SM_A   0
#define SM_B   (3 * STG)                   // 49152
#define GEMM_SMEM (SM_B + 3 * STG)         // 98304 = 96KB -> 2 CTAs/SM

template <int MODE>
__device__ __forceinline__ void gemm_tile(
    const __half* __restrict__ A, const __half* __restrict__ Bt,
    const float* __restrict__ vec, const float* __restrict__ resid,
    __half* __restrict__ Cv, char* smem, int bx, int by) {
    const uint32_t sbase = smem_u32(smem);

    const int tid = threadIdx.x;
    const int wid = tid >> 5, lane = tid & 31;
    const int row0 = by * TILE_M;
    const int col0 = bx * TILE_N;
    const int wm = (wid & 3) * 32;
    const int wn = (wid >> 2) * 64;
    const int lq = lane >> 2;              // 0..7
    const int lr = lane & 3;               // 0..3

    const char* Ab = (const char*)A + (size_t)by * NSTH * 16384;
    const char* Bb = (const char*)Bt + (size_t)bx * NSTH * 16384;
    const int frow = tid >> 3;             // 0..31
    const int fq = tid & 7;
    const uint32_t stchunk = (uint32_t)((fq ^ swz8(frow)) << 4);
    const uint32_t dA0 = sbase + SM_A + frow * 128 + stchunk;
    const uint32_t dB0 = sbase + SM_B + frow * 128 + stchunk;
    const size_t gsrc = (size_t)frow * 128 + fq * 16;

    const int swzl = swz8(lq);
    const int cc0 = (lr ^ swzl) << 4;
    const int cc1 = ((4 + lr) ^ swzl) << 4;

    const int aoff = (wm + lq) * 128;
    const int boff = (wn + lq) * 128;

    float acc[2][8][4];
    #pragma unroll
    for (int mt = 0; mt < 2; ++mt)
        #pragma unroll
        for (int nt = 0; nt < 8; ++nt)
            #pragma unroll
            for (int j = 0; j < 4; ++j) acc[mt][nt][j] = 0.f;

    #pragma unroll
    for (int p = 0; p < 2; ++p) {
        const char* as = Ab + (size_t)p * 16384;
        const char* bs = Bb + (size_t)p * 16384;
        #pragma unroll
        for (int i = 0; i < 4; ++i) {
            CP_ASYNC16(dA0 + p * STG + i * 4096, as + gsrc + (size_t)i * 4096);
            CP_ASYNC16(dB0 + p * STG + i * 4096, bs + gsrc + (size_t)i * 4096);
        }
        CP_COMMIT();
    }

    #pragma unroll
    for (int s = 0; s < NSTH; ++s) {
        const int buf = s % 3;
        if (s == NSTH - 1) { CP_WAIT0(); } else { CP_WAIT1(); }
        __syncthreads();
        if (s + 2 < NSTH) {
            const int bufn = (s + 2) % 3;
            const char* as = Ab + (size_t)(s + 2) * 16384;
            const char* bs = Bb + (size_t)(s + 2) * 16384;
            #pragma unroll
            for (int i = 0; i < 4; ++i) {
                CP_ASYNC16(dA0 + bufn * STG + i * 4096, as + gsrc + (size_t)i * 4096);
                CP_ASYNC16(dB0 + bufn * STG + i * 4096, bs + gsrc + (size_t)i * 4096);
            }
            CP_COMMIT();
        }

        const char* sa = smem + SM_A + buf * STG + aoff;
        const char* sb = smem + SM_B + buf * STG + boff;

        #pragma unroll
        for (int c = 0; c < 2; ++c) {
            const int co = c ? cc1 : cc0;
            uint4 qa0[2], qa1[2];
            #pragma unroll
            for (int mt = 0; mt < 2; ++mt) {
                qa0[mt] = *(const uint4*)(sa + mt * 2048 + co);
                qa1[mt] = *(const uint4*)(sa + mt * 2048 + 1024 + co);
            }
            uint32_t ag0[2][4], ag1[2][4];
            #pragma unroll
            for (int mt = 0; mt < 2; ++mt) {
                ag0[mt][0] = qa0[mt].x; ag0[mt][1] = qa1[mt].x;
                ag0[mt][2] = qa0[mt].y; ag0[mt][3] = qa1[mt].y;
                ag1[mt][0] = qa0[mt].z; ag1[mt][1] = qa1[mt].z;
                ag1[mt][2] = qa0[mt].w; ag1[mt][3] = qa1[mt].w;
            }
            uint4 pb = *(const uint4*)(sb + co);
            #pragma unroll
            for (int nt = 0; nt < 8; ++nt) {
                uint4 pc = pb;
                if (nt < 7)
                    pb = *(const uint4*)(sb + (nt + 1) * 1024 + co);
                uint32_t bg0[2] = { pc.x, pc.y };
                uint32_t bg1[2] = { pc.z, pc.w };
                mma_f16_16x8x16(acc[0][nt], ag0[0], bg0);
                mma_f16_16x8x16(acc[1][nt], ag0[1], bg0);
                mma_f16_16x8x16(acc[0][nt], ag1[0], bg1);
                mma_f16_16x8x16(acc[1][nt], ag1[1], bg1);
            }
        }
    }

    // ---------------- Epilogue: packed 16B interleaved stores ----------------
    const float* vbase = (MODE == 2) ? (vec + (size_t)(row0 / T_) * D_ + col0)
                                     : (vec + col0);
    const size_t tilebase = (size_t)by * NSTH * 8192;   // halves
    const int wnidx = wid >> 2;

    #pragma unroll
    for (int mt = 0; mt < 2; ++mt) {
        int r = wm + mt * 16 + lq;
        float s0 = 0.f, q0 = 0.f, s1 = 0.f, q1 = 0.f;
        #pragma unroll
        for (int pack = 0; pack < 2; ++pack) {
            int kabs = col0 + wn + pack * 32;
            size_t off = tilebase + (size_t)(kabs >> 6) * 8192
                         + (size_t)r * 64 + ((kabs & 63) >> 5) * 32 + lr * 8;
            __align__(16) __half2 h0[4];
            __align__(16) __half2 h1[4];
            #pragma unroll
            for (int q = 0; q < 4; ++q) {
                int nt = pack * 4 + q;
                int col = wn + nt * 8 + lr * 2;
                float b0 = vbase[col], b1 = vbase[col + 1];
                if (MODE == 0) {
                    h0[q] = __floats2half2_rn(tanhf(acc[mt][nt][0] + b0),
                                              tanhf(acc[mt][nt][1] + b1));
                    h1[q] = __floats2half2_rn(tanhf(acc[mt][nt][2] + b0),
                                              tanhf(acc[mt][nt][3] + b1));
                } else {
                    int row = row0 + r;
                    float2 rd0 = *(const float2*)(resid + (size_t)row * D_ + col0 + col);
                    float2 rd1 = *(const float2*)(resid + (size_t)(row + 8) * D_ + col0 + col);
                    float x0 = tanhf(b0 - acc[mt][nt][0]) + rd0.x;
                    float x1 = tanhf(b1 - acc[mt][nt][1]) + rd0.y;
                    float x2 = tanhf(b0 - acc[mt][nt][2]) + rd1.x;
                    float x3 = tanhf(b1 - acc[mt][nt][3]) + rd1.y;
                    s0 += x0 + x1; q0 += x0 * x0 + x1 * x1;
                    s1 += x2 + x3; q1 += x2 * x2 + x3 * x3;
                    h0[q] = __floats2half2_rn(x0, x1);
                    h1[q] = __floats2half2_rn(x2, x3);
                }
            }
            *(uint4*)(Cv + off)       = *(const uint4*)h0;
            *(uint4*)(Cv + off + 512) = *(const uint4*)h1;     // row r+8
        }
        if (MODE == 2) {
            #pragma unroll
            for (int o = 1; o <= 2; o <<= 1) {
                s0 += __shfl_xor_sync(0xffffffffu, s0, o);
                q0 += __shfl_xor_sync(0xffffffffu, q0, o);
                s1 += __shfl_xor_sync(0xffffffffu, s1, o);
                q1 += __shfl_xor_sync(0xffffffffu, q1, o);
            }
            if (lr == 0) {
                int row = row0 + r;
                g_stats[((size_t)row * 4 + bx) * 2 + wnidx] = make_float2(s0, q0);
                g_stats[((size_t)(row + 8) * 4 + bx) * 2 + wnidx] = make_float2(s1, q1);
            }
        }
    }
}

// ---------------------------------------------------------------------------
// gemm_fused: phase 0 = gemm0 tile (H), per-row-block flag sync,
//             phase 1 = gemm2 tile (x + LN stats). Grid (4, 256).
// ---------------------------------------------------------------------------
__global__ __launch_bounds__(GM_THREADS, 2)
void gemm_fused(const __half* __restrict__ cumA, const __half* __restrict__ WtHist,
                const float* __restrict__ bias,
                const __half* __restrict__ Wc, const float* __restrict__ vec2,
                const float* __restrict__ resid,
                __half* __restrict__ H, __half* __restrict__ X) {
    extern __shared__ char smem[];
    const int bx = blockIdx.x, by = blockIdx.y;

    // phase 0: H tile
    gemm_tile<0>(cumA, WtHist, bias, nullptr, H, smem, bx, by);
    __threadfence();
    __syncthreads();
    if (threadIdx.x == 0) {
        atomicAdd(&g_sync[by], 1);
        while (atomicAdd(&g_sync[by], 0) < 4) { }
    }
    __syncthreads();

    // phase 1: x tile (A = H row-block by, now complete)
    gemm_tile<2>(H, Wc, vec2, resid, X, smem, bx, by);
}

// ---------------------------------------------------------------------------
// LayerNorm normalize pass: stats precomputed; packed fp16 x -> fp32 out
// ---------------------------------------------------------------------------
__global__ __launch_bounds__(256)
void layernorm_kernel(const __half* __restrict__ X,
                      const float* __restrict__ gamma,
                      const float* __restrict__ beta,
                      float* __restrict__ out) {
    int row = blockIdx.x;
    int tid = threadIdx.x;

    float sum = 0.f, sq = 0.f;
    #pragma unroll
    for (int i = 0; i < 8; ++i) {
        float2 st = g_stats[(size_t)row * 8 + i];
        sum += st.x; sq += st.y;
    }
    float mu = sum * (1.0f / D_);
    float var = sq * (1.0f / D_) - mu * mu;
    float rstd = rsqrtf(var + 1e-6f);

    int p = tid * 2;
    int kb = p >> 6;
    int within = p & 63;
    int chunk = within >> 5;
    int p32 = within & 31;
    int lr = p32 >> 3;
    int q = (p32 >> 1) & 3;
    size_t addr = ((size_t)(row >> 7) * NSTH + kb) * 8192
                  + (size_t)(row & 127) * 64 + chunk * 32 + p32;
    __half2 hv = *(const __half2*)(X + addr);
    int col = kb * 64 + chunk * 32 + q * 8 + lr * 2;
    float2 g = *(const float2*)(gamma + col);
    float2 be = *(const float2*)(beta + col);
    float2 o;
    o.x = (__low2float(hv)  - mu) * rstd * g.x + be.x;
    o.y = (__high2float(hv) - mu) * rstd * g.y + be.y;
    *(float2*)(out + (size_t)row * D_ + col) = o;
}

// ---------------------------------------------------------------------------
// Launcher — launch index 3 = gemm_fused (the ncu-profiled slot region)
// ---------------------------------------------------------------------------
extern "C" void kernel_launch(void* const* d_in, const int* in_sizes, int n_in,
                              void* d_out, int out_size) {
    const float* summ   = (const float*)d_in[0];
    const float* dec    = (const float*)d_in[1];
    const float* W_hist = (const float*)d_in[2];
    const float* b_hist = (const float*)d_in[3];
    const float* W1     = (const float*)d_in[4];
    const float* W2     = (const float*)d_in[5];
    const float* W_out  = (const float*)d_in[6];
    const float* b_out  = (const float*)d_in[7];
    const float* gamma  = (const float*)d_in[8];
    const float* beta   = (const float*)d_in[9];
    float* out = (float*)d_out;

    __half *hbufA, *hbufB, *hwt;
    float *summ2;
    int* syncp;
    cudaGetSymbolAddress((void**)&hbufA, g_hbufA);
    cudaGetSymbolAddress((void**)&hbufB, g_hbufB);
    cudaGetSymbolAddress((void**)&summ2, g_summ2);
    cudaGetSymbolAddress((void**)&hwt,   g_hWt);
    cudaGetSymbolAddress((void**)&syncp, g_sync);
    __half* WtHist = hwt;
    __half* Wc     = hwt + (size_t)D_ * D_;

    cudaFuncSetAttribute(gemm_fused, cudaFuncAttributeMaxDynamicSharedMemorySize, GEMM_SMEM);

    // reset H-ready flags (captured async memset, no allocation)
    cudaMemsetAsync(syncp, 0, (M_TOTAL / 128) * sizeof(int));

    // 0: chunk sums + Wc=W2@W_out + summ_proj (all independent)
    pre0_kernel<<<416, 512>>>(dec, summ, W1, W2, W_out);
    // 1: prefix + W_hist transpose + sp2
    prep_kernel<<<296, 512>>>(W_hist, W_out, b_out);
    // 2: causal running mean -> hbufA (fp16, interleaved)
    cum_mean_kernel<<<B_ * NCHUNK, D_>>>(dec);

    // 3: fused GEMM chain: H = tanh(cum@W_hist + b); x = tanh(sp2 - H@Wc) + dec
    dim3 ggrid(D_ / TILE_N, M_TOTAL / TILE_M);   // (4, 256)
    gemm_fused<<<ggrid, GM_THREADS, GEMM_SMEM>>>(hbufA, WtHist, b_hist,
                                                 Wc, summ2, dec, hbufB, hbufA);

    // 4: LayerNorm normalize pass
    layernorm_kernel<<<M_TOTAL, 256>>>(hbufA, gamma, beta, out);
}